// round 7
// baseline (speedup 1.0000x reference)
#include <cuda_runtime.h>
#include <math.h>
#include <stdint.h>

#define NPTS 4096
#define NB   2
#define NN   (NPTS*NB)      // 8192 nodes
#define DIM  64
#define KNN  5
#define TOPM 10             // approx candidates refined exactly
#define NKM  (NPTS*KNN)
#define NEDGE (NKM*NB)
#define NT   32             // 128-wide tiles per side
#define NITEMS_B (NT*(NT+1)/2)   // 528
#define NITEMS   (NB*NITEMS_B)   // 1056

#define KSTRIDE 136
#define BUF (32*KSTRIDE)            // floats per staging buffer (4352)
#define SMEMT ((4*BUF + 256)*4)     // 70656 bytes
#define DPAD 132

typedef unsigned long long ull;

// -------- scratch (static device globals) ----------
__device__ float g_X1 [NN*DIM];
__device__ float g_GE1[NN*DIM];
__device__ float g_GE2[NN*DIM];
__device__ float g_GEH[NN*DIM];     // tf32-hi of current layer's GE
__device__ float g_GEL[NN*DIM];     // tf32-lo
__device__ float g_SQ [NN];
__device__ ull   g_CAND[(size_t)NN*NT*KNN];
__device__ int   g_NBR[NN*KNN];
__device__ float g_A  [NN*DIM];
__device__ float g_B  [NN*DIM];
__device__ float g_ACC1[NN*DIM];
__device__ float g_ACC2[NN*DIM];

__device__ __forceinline__ void tf32_split(float x, float &hi, float &lo) {
    uint32_t hb;
    asm("cvt.rna.tf32.f32 %0, %1;" : "=r"(hb) : "f"(x));
    hi = __uint_as_float(hb);
    float l = x - hi;
    uint32_t lb;
    asm("cvt.rna.tf32.f32 %0, %1;" : "=r"(lb) : "f"(l));
    lo = __uint_as_float(lb);
}

// warp-level tf32 MMA (legacy HMMA path; target sm_80+, works on sm_103)
__device__ __forceinline__ void mma_tf32(float c[4], const uint32_t a[4],
                                         uint32_t b0, uint32_t b1) {
    asm volatile(
        "mma.sync.aligned.m16n8k8.row.col.f32.tf32.tf32.f32 "
        "{%0,%1,%2,%3}, {%4,%5,%6,%7}, {%8,%9}, {%0,%1,%2,%3};"
        : "+f"(c[0]), "+f"(c[1]), "+f"(c[2]), "+f"(c[3])
        : "r"(a[0]), "r"(a[1]), "r"(a[2]), "r"(a[3]), "r"(b0), "r"(b1));
}

// ---------------- pre_fc + embed1 + sq + tf32 split ----------------
__global__ void k_prefc(const float* __restrict__ x,
                        const float* __restrict__ Wp, const float* __restrict__ bp,
                        const float* __restrict__ Wd, const float* __restrict__ bd) {
    int v = blockIdx.x;
    int o = threadIdx.x;           // 64 threads
    __shared__ float xr[32];
    __shared__ float x1r[64];
    __shared__ float red[64];
    if (o < 32) xr[o] = x[v*32 + o];
    __syncthreads();
    float acc = bp[o];
#pragma unroll
    for (int d = 0; d < 32; d++) acc = fmaf(xr[d], Wp[d*64 + o], acc);
    acc = acc > 0.f ? acc : 0.1f * acc;
    g_X1[v*64 + o] = acc;
    x1r[o] = acc;
    __syncthreads();
    float ge = bd[o];
#pragma unroll
    for (int d = 0; d < 64; d++) ge = fmaf(x1r[d], Wd[d*64 + o], ge);
    g_GE1[v*64 + o] = ge;
    float hi, lo;
    tf32_split(ge, hi, lo);
    g_GEH[v*64 + o] = hi;
    g_GEL[v*64 + o] = lo;
    red[o] = ge * ge;
    __syncthreads();
    for (int s = 32; s > 0; s >>= 1) { if (o < s) red[o] += red[o + s]; __syncthreads(); }
    if (o == 0) g_SQ[v] = red[0];
}

// ---------------- embed2 + sq + tf32 split ----------------
__global__ void k_embed2(const float* __restrict__ Wd, const float* __restrict__ bd) {
    int v = blockIdx.x, o = threadIdx.x;   // 64 threads
    __shared__ float gr[128];
    __shared__ float red[64];
    gr[o]      = g_GE1 [v*64 + o];
    gr[64 + o] = g_ACC1[v*64 + o];
    __syncthreads();
    float ge = bd[o];
#pragma unroll
    for (int d = 0; d < 128; d++) ge = fmaf(gr[d], Wd[d*64 + o], ge);
    g_GE2[v*64 + o] = ge;
    float hi, lo;
    tf32_split(ge, hi, lo);
    g_GEH[v*64 + o] = hi;
    g_GEL[v*64 + o] = lo;
    red[o] = ge * ge;
    __syncthreads();
    for (int s = 32; s > 0; s >>= 1) { if (o < s) red[o] += red[o + s]; __syncthreads(); }
    if (o == 0) g_SQ[v] = red[0];
}

// ---- merge two sorted 5-lists held by adjacent lanes (xor 1) ----
__device__ __forceinline__ void merge_pair(ull best[KNN]) {
    ull other[KNN];
#pragma unroll
    for (int j = 0; j < KNN; j++) other[j] = __shfl_xor_sync(0xffffffffu, best[j], 1);
#pragma unroll
    for (int j = 0; j < KNN; j++) {
        ull key = other[j];
        if (key < best[KNN-1]) {
            best[KNN-1] = key;
#pragma unroll
            for (int u = KNN-1; u > 0; u--)
                if (best[u] < best[u-1]) {
                    ull t2 = best[u]; best[u] = best[u-1]; best[u-1] = t2;
                }
        }
    }
}

// ============ tensor-core (mma.sync tf32 x3) distance tile + top-5 ============
__global__ void __launch_bounds__(256, 2)
k_tile() {
    extern __shared__ float sm[];
    float* Ah = sm;
    float* Al = sm + BUF;
    float* Bh = sm + 2*BUF;
    float* Bl = sm + 3*BUF;
    float* sqr_s = sm + 4*BUF;        // 128 floats
    float* sqc_s = sqr_s + 128;       // 128 floats

    int item = blockIdx.x;
    int bb  = item / NITEMS_B;
    int tri = item - bb*NITEMS_B;
    int rt = 0;
    while (tri >= NT - rt) { tri -= NT - rt; rt++; }
    int ct = rt + tri;

    int tid = threadIdx.x;
    int wid = tid >> 5, lane = tid & 31;
    int g = lane >> 2, tig = lane & 3;
    int wr = wid & 3, wh = wid >> 2;

    if (tid < 128) sqr_s[tid] = g_SQ[bb*NPTS + rt*128 + tid];
    else           sqc_s[tid-128] = g_SQ[bb*NPTS + ct*128 + (tid-128)];

    const float4* GH = (const float4*)g_GEH;
    const float4* GL = (const float4*)g_GEL;
    size_t abase = (size_t)(bb*NPTS + rt*128) * 16;   // float4 units
    size_t bbase = (size_t)(bb*NPTS + ct*128) * 16;

    float acc[2][8][4];
#pragma unroll
    for (int s = 0; s < 2; s++)
#pragma unroll
        for (int nb = 0; nb < 8; nb++)
#pragma unroll
            for (int j = 0; j < 4; j++) acc[s][nb][j] = 0.f;

#pragma unroll
    for (int chunk = 0; chunk < 2; chunk++) {
        if (chunk) __syncthreads();
#pragma unroll
        for (int it = 0; it < 16; it++) {
            int idx = tid + it*256;        // 0..4095
            int buf = idx >> 10;
            int rem = idx & 1023;
            int row = rem & 127, q = rem >> 7;
            const float4* src = (buf == 0) ? GH + abase : (buf == 1) ? GL + abase
                              : (buf == 2) ? GH + bbase : GL + bbase;
            float4 v = src[row*16 + chunk*8 + q];
            float* d = sm + buf*BUF;
            d[(q*4+0)*KSTRIDE + row] = v.x;
            d[(q*4+1)*KSTRIDE + row] = v.y;
            d[(q*4+2)*KSTRIDE + row] = v.z;
            d[(q*4+3)*KSTRIDE + row] = v.w;
        }
        __syncthreads();
#pragma unroll
        for (int kb = 0; kb < 4; kb++) {
            int k0 = kb*8;
            uint32_t ah[2][4], al[2][4];
#pragma unroll
            for (int s = 0; s < 2; s++) {
                int r0 = wr*32 + s*16;
                ah[s][0] = __float_as_uint(Ah[(k0+tig  )*KSTRIDE + r0+g  ]);
                ah[s][1] = __float_as_uint(Ah[(k0+tig  )*KSTRIDE + r0+g+8]);
                ah[s][2] = __float_as_uint(Ah[(k0+tig+4)*KSTRIDE + r0+g  ]);
                ah[s][3] = __float_as_uint(Ah[(k0+tig+4)*KSTRIDE + r0+g+8]);
                al[s][0] = __float_as_uint(Al[(k0+tig  )*KSTRIDE + r0+g  ]);
                al[s][1] = __float_as_uint(Al[(k0+tig  )*KSTRIDE + r0+g+8]);
                al[s][2] = __float_as_uint(Al[(k0+tig+4)*KSTRIDE + r0+g  ]);
                al[s][3] = __float_as_uint(Al[(k0+tig+4)*KSTRIDE + r0+g+8]);
            }
#pragma unroll
            for (int nb = 0; nb < 8; nb++) {
                int c0 = wh*64 + nb*8;
                uint32_t bh0 = __float_as_uint(Bh[(k0+tig  )*KSTRIDE + c0+g]);
                uint32_t bh1 = __float_as_uint(Bh[(k0+tig+4)*KSTRIDE + c0+g]);
                uint32_t bl0 = __float_as_uint(Bl[(k0+tig  )*KSTRIDE + c0+g]);
                uint32_t bl1 = __float_as_uint(Bl[(k0+tig+4)*KSTRIDE + c0+g]);
#pragma unroll
                for (int s = 0; s < 2; s++) {
                    mma_tf32(acc[s][nb], ah[s], bh0, bh1);   // hi*hi
                    mma_tf32(acc[s][nb], ah[s], bl0, bl1);   // hi*lo
                    mma_tf32(acc[s][nb], al[s], bh0, bh1);   // lo*hi
                }
            }
        }
    }
    __syncthreads();

    // ---- dots -> Ds (overlays staging buffers) ----
    float* Ds = sm;
#pragma unroll
    for (int s = 0; s < 2; s++) {
        int r0 = wr*32 + s*16;
#pragma unroll
        for (int nb = 0; nb < 8; nb++) {
            int col = wh*64 + nb*8 + tig*2;
            float2 lo2 = {acc[s][nb][0], acc[s][nb][1]};
            float2 hi2 = {acc[s][nb][2], acc[s][nb][3]};
            *(float2*)(Ds + (r0+g  )*DPAD + col) = lo2;
            *(float2*)(Ds + (r0+g+8)*DPAD + col) = hi2;
        }
    }
    __syncthreads();

    // ---- row scan: 2 threads/row, interleaved cols, shfl-pair merge ----
    {
        int r = tid >> 1, h = tid & 1;
        float sqr = sqr_s[r];
        ull best[KNN];
#pragma unroll
        for (int j = 0; j < KNN; j++) best[j] = ~0ULL;
        for (int c2 = 0; c2 < 64; c2++) {
            int col = h + 2*c2;
            float d = fmaxf(sqr + sqc_s[col] - 2.f*Ds[r*DPAD + col], 0.f);
            ull key = ((ull)__float_as_uint(d) << 32) | (unsigned)(ct*128 + col);
            if (key < best[KNN-1]) {
                best[KNN-1] = key;
#pragma unroll
                for (int j = KNN-1; j > 0; j--)
                    if (best[j] < best[j-1]) {
                        ull t2 = best[j]; best[j] = best[j-1]; best[j-1] = t2;
                    }
            }
        }
        merge_pair(best);
        if (h == 0) {
            size_t rowg = (size_t)(bb*NPTS + rt*128 + r);
#pragma unroll
            for (int j = 0; j < KNN; j++) g_CAND[(rowg*NT + ct)*KNN + j] = best[j];
        }
    }
    // ---- col scan (off-diagonal) ----
    if (rt != ct) {
        int c = tid >> 1, h = tid & 1;
        float sqc = sqc_s[c];
        ull best[KNN];
#pragma unroll
        for (int j = 0; j < KNN; j++) best[j] = ~0ULL;
        for (int r2 = 0; r2 < 64; r2++) {
            int row = h + 2*r2;
            float d = fmaxf(sqr_s[row] + sqc - 2.f*Ds[row*DPAD + c], 0.f);
            ull key = ((ull)__float_as_uint(d) << 32) | (unsigned)(rt*128 + row);
            if (key < best[KNN-1]) {
                best[KNN-1] = key;
#pragma unroll
                for (int j = KNN-1; j > 0; j--)
                    if (best[j] < best[j-1]) {
                        ull t2 = best[j]; best[j] = best[j-1]; best[j-1] = t2;
                    }
            }
        }
        merge_pair(best);
        if (h == 0) {
            size_t rowg = (size_t)(bb*NPTS + ct*128 + c);
#pragma unroll
            for (int j = 0; j < KNN; j++) g_CAND[(rowg*NT + rt)*KNN + j] = best[j];
        }
    }
}

// -------- merge 32 approx 5-lists -> top-10, refine with exact fp32, logprobs --------
__global__ void k_merge_lp(int layer, const float* __restrict__ tptr,
                           float* __restrict__ lp_out) {
    int gw   = (blockIdx.x * blockDim.x + threadIdx.x) >> 5;   // row
    int lane = threadIdx.x & 31;
    if (gw >= NN) return;
    int bb = gw >> 12, jj = gw & 4095;
    const ull* cp = g_CAND + ((size_t)gw*NT + lane)*KNN;
    ull keys[KNN];
#pragma unroll
    for (int j = 0; j < KNN; j++) keys[j] = cp[j];

    // extract top-TOPM approx candidates (warp-min rounds; keys unique)
    unsigned candidx[TOPM];
#pragma unroll
    for (int r = 0; r < TOPM; r++) {
        ull cand = keys[0];
        ull m = cand;
#pragma unroll
        for (int off = 16; off; off >>= 1) {
            ull o = __shfl_xor_sync(0xffffffffu, m, off);
            if (o < m) m = o;
        }
        if (m == cand) {
#pragma unroll
            for (int j = 0; j < KNN-1; j++) keys[j] = keys[j+1];
            keys[KNN-1] = ~0ULL;
        }
        candidx[r] = (unsigned)(m & 0xffffffffu);
    }

    // exact fp32 expansion-form distances for the TOPM candidates
    const float* GE = layer ? g_GE2 : g_GE1;
    const float* gp = GE + (size_t)gw*DIM;
    float gp0 = gp[lane], gp1 = gp[lane + 32];
    float sqp = g_SQ[gw];
    ull ekeys[TOPM];
#pragma unroll
    for (int r = 0; r < TOPM; r++) {
        int a = (int)candidx[r];
        const float* ga = GE + (size_t)(bb*NPTS + a)*DIM;
        float s = ga[lane]*gp0;
        s = fmaf(ga[lane+32], gp1, s);
#pragma unroll
        for (int off = 16; off; off >>= 1) s += __shfl_xor_sync(0xffffffffu, s, off);
        float dist = fmaxf(g_SQ[bb*NPTS + a] + sqp - 2.f*s, 0.f);
        // insertion sort by exact key
        ull key = ((ull)__float_as_uint(dist) << 32) | (unsigned)a;
        int j = r;
        while (j > 0 && ekeys[j-1] > key) { ekeys[j] = ekeys[j-1]; j--; }
        ekeys[j] = key;
    }

    unsigned nbr[KNN];
#pragma unroll
    for (int r = 0; r < KNN; r++) {
        nbr[r] = (unsigned)(ekeys[r] & 0xffffffffu);
        if (lane == 0) g_NBR[gw*KNN + r] = (int)nbr[r];
    }

    // logprobs (exact fp32, faithful scrambled layout)
    float tv = tptr[0]; tv = fminf(fmaxf(tv, -5.f), 5.f);
    float t = expf(tv);
#pragma unroll
    for (int r = 0; r < KNN; r++) {
        int a  = (int)nbr[r];
        int mf = r*NPTS + jj;
        int p  = mf / KNN, q = mf - p*KNN;
        const float* ga = GE + (size_t)(bb*NPTS + a)*DIM;
        const float* gq = GE + (size_t)(bb*NPTS + p)*DIM;
        float s = 0.f;
#pragma unroll
        for (int u = 0; u < 2; u++) {
            float d = ga[lane + 32*u] - gq[lane + 32*u];
            s = fmaf(d, d, s);
        }
#pragma unroll
        for (int off = 16; off; off >>= 1) s += __shfl_xor_sync(0xffffffffu, s, off);
        if (lane == 0)
            lp_out[((bb*NPTS + p)*KNN + q)*2 + layer] = -s * t;
    }
}

// ------- EdgeConv node pre-GEMM: 16 nodes x 128 outs per block, grid 512 -------
__global__ void __launch_bounds__(256)
k_AB(int layer, const float* __restrict__ W) {
    __shared__ float Ws[64*128];     // [k][col]: col<64 -> Wtop-Wbot, col>=64 -> Wbot
    __shared__ float Xs[16*65];
    const float* X = layer ? g_ACC1 : g_X1;
    float* ACC = layer ? g_ACC2 : g_ACC1;
    int tid = threadIdx.x;
    int nt = blockIdx.x;
#pragma unroll
    for (int i = 0; i < 32; i++) {
        int idx = tid + i*256;
        int k = idx >> 7, col = idx & 127;
        float val = (col < 64) ? (W[k*64 + col] - W[(64 + k)*64 + col])
                               : W[(64 + k)*64 + (col - 64)];
        Ws[idx] = val;
    }
#pragma unroll
    for (int i = 0; i < 4; i++) {
        int idx = tid + i*256;
        Xs[(idx >> 6)*65 + (idx & 63)] = X[(size_t)nt*16*64 + idx];
    }
    __syncthreads();
    int n = tid >> 4, og = tid & 15;
    const float4* Ws4 = (const float4*)Ws;
    float acc[8];
#pragma unroll
    for (int j = 0; j < 8; j++) acc[j] = 0.f;
#pragma unroll 8
    for (int k = 0; k < 64; k++) {
        float av = Xs[n*65 + k];
        float4 b0 = Ws4[k*32 + og*2];
        float4 b1 = Ws4[k*32 + og*2 + 1];
        acc[0] = fmaf(av, b0.x, acc[0]);
        acc[1] = fmaf(av, b0.y, acc[1]);
        acc[2] = fmaf(av, b0.z, acc[2]);
        acc[3] = fmaf(av, b0.w, acc[3]);
        acc[4] = fmaf(av, b1.x, acc[4]);
        acc[5] = fmaf(av, b1.y, acc[5]);
        acc[6] = fmaf(av, b1.z, acc[6]);
        acc[7] = fmaf(av, b1.w, acc[7]);
    }
    int node = nt*16 + n;
    float4 lo = {acc[0], acc[1], acc[2], acc[3]};
    float4 hi = {acc[4], acc[5], acc[6], acc[7]};
    if (og < 8) {
        *(float4*)(g_A + (size_t)node*64 + og*8)     = lo;
        *(float4*)(g_A + (size_t)node*64 + og*8 + 4) = hi;
        float4 z = {0.f, 0.f, 0.f, 0.f};
        *(float4*)(ACC + (size_t)node*64 + og*8)     = z;
        *(float4*)(ACC + (size_t)node*64 + og*8 + 4) = z;
    } else {
        int c = (og - 8)*8;
        *(float4*)(g_B + (size_t)node*64 + c)     = lo;
        *(float4*)(g_B + (size_t)node*64 + c + 4) = hi;
    }
}

// ---------------- EdgeConv scatter-max ----------------
__global__ void k_scatter(int layer, const float* __restrict__ bias) {
    int tid = blockIdx.x * blockDim.x + threadIdx.x;
    if (tid >= NEDGE * 2) return;
    int s  = tid >> 1, h = tid & 1;
    int p0 = s >> 2, bb = (s >> 1) & 1, c = s & 1;
    int src, dst;
    if (c == 0) src = g_NBR[(bb*NPTS + (p0 & 4095))*KNN + (p0 >> 12)] + bb*NPTS;
    else        src = p0 / KNN + bb*NPTS;
    int p1 = p0 + NKM/2;
    if (c == 0) dst = g_NBR[(bb*NPTS + (p1 & 4095))*KNN + (p1 >> 12)] + bb*NPTS;
    else        dst = p1 / KNN + bb*NPTS;

    float* ACC = layer ? g_ACC2 : g_ACC1;
    const float4* Ad = (const float4*)(g_A + dst*64 + h*32);
    const float4* Bv = (const float4*)(g_B + src*64 + h*32);
    const float4* Bi = (const float4*)(bias + h*32);
    int* out = (int*)(ACC + dst*64 + h*32);
#pragma unroll
    for (int o = 0; o < 8; o++) {
        float4 av = Ad[o], bv = Bv[o], bi = Bi[o];
        float m0 = av.x + bv.x + bi.x;
        float m1 = av.y + bv.y + bi.y;
        float m2 = av.z + bv.z + bi.z;
        float m3 = av.w + bv.w + bi.w;
        if (m0 > 0.f) atomicMax(&out[o*4 + 0], __float_as_int(m0));
        if (m1 > 0.f) atomicMax(&out[o*4 + 1], __float_as_int(m1));
        if (m2 > 0.f) atomicMax(&out[o*4 + 2], __float_as_int(m2));
        if (m3 > 0.f) atomicMax(&out[o*4 + 3], __float_as_int(m3));
    }
}

// ---------------- final MLP 64 -> 32 -> 8 ----------------
__global__ void k_fc(const float* __restrict__ W1, const float* __restrict__ b1,
                     const float* __restrict__ W2, const float* __restrict__ b2,
                     float* __restrict__ out) {
    int v = blockIdx.x, o = threadIdx.x;   // 32 threads
    __shared__ float xr[64];
    __shared__ float hr[32];
    xr[o]      = g_ACC2[v*64 + o];
    xr[32 + o] = g_ACC2[v*64 + 32 + o];
    __syncthreads();
    float hh = b1[o];
#pragma unroll
    for (int d = 0; d < 64; d++) hh = fmaf(xr[d], W1[d*32 + o], hh);
    hh = hh > 0.f ? hh : 0.1f * hh;
    hr[o] = hh;
    __syncthreads();
    if (o < 8) {
        float acc = b2[o];
#pragma unroll
        for (int d = 0; d < 32; d++) acc = fmaf(hr[d], W2[d*8 + o], acc);
        out[v*8 + o] = acc;
    }
}

// ======================= launcher =======================
extern "C" void kernel_launch(void* const* d_in, const int* in_sizes, int n_in,
                              void* d_out, int out_size) {
    const float* x     = (const float*)d_in[0];
    const float* W_pre = (const float*)d_in[1];
    const float* b_pre = (const float*)d_in[2];
    const float* W_d1  = (const float*)d_in[3];
    const float* b_d1  = (const float*)d_in[4];
    const float* t1    = (const float*)d_in[5];
    const float* W_c1  = (const float*)d_in[6];
    const float* b_c1  = (const float*)d_in[7];
    const float* W_d2  = (const float*)d_in[8];
    const float* b_d2  = (const float*)d_in[9];
    const float* t2    = (const float*)d_in[10];
    const float* W_c2  = (const float*)d_in[11];
    const float* b_c2  = (const float*)d_in[12];
    const float* W_f1  = (const float*)d_in[13];
    const float* b_f1  = (const float*)d_in[14];
    const float* W_f2  = (const float*)d_in[15];
    const float* b_f2  = (const float*)d_in[16];

    float* out = (float*)d_out;                 // [2,4096,8]
    float* lp  = out + NN * 8;                  // [2,4096,5,2]

    cudaFuncSetAttribute(k_tile, cudaFuncAttributeMaxDynamicSharedMemorySize, SMEMT);

    // layer 1
    k_prefc<<<NN, 64>>>(x, W_pre, b_pre, W_d1, b_d1);
    k_tile<<<NITEMS, 256, SMEMT>>>();
    k_merge_lp<<<NN/8, 256>>>(0, t1, lp);
    k_AB<<<NN/16, 256>>>(0, W_c1);
    k_scatter<<<(NEDGE*2 + 255)/256, 256>>>(0, b_c1);

    // layer 2
    k_embed2<<<NN, 64>>>(W_d2, b_d2);
    k_tile<<<NITEMS, 256, SMEMT>>>();
    k_merge_lp<<<NN/8, 256>>>(1, t2, lp);
    k_AB<<<NN/16, 256>>>(1, W_c2);
    k_scatter<<<(NEDGE*2 + 255)/256, 256>>>(1, b_c2);

    // head
    k_fc<<<NN, 32>>>(W_f1, b_f1, W_f2, b_f2, out);
}

// round 8
// speedup vs baseline: 1.1744x; 1.1744x over previous
#include <cuda_runtime.h>
#include <math.h>
#include <stdint.h>

#define NPTS 4096
#define NB   2
#define NN   (NPTS*NB)      // 8192 nodes
#define DIM  64
#define KNN  5
#define NKM  (NPTS*KNN)
#define NEDGE (NKM*NB)
#define NT   32
#define NITEMS_B (NT*(NT+1)/2)   // 528
#define NITEMS   (NB*NITEMS_B)   // 1056

#define PADW 132
#define SMEMF ((32*128*2 + 128*PADW)*4)   // 100352 bytes -> 2 blocks/SM
#define SMEMAB ((64*68 + 64*136)*4)       // 52224 bytes for k_AB

typedef unsigned long long ull;

// -------- scratch (static device globals) ----------
__device__ float g_X1 [NN*DIM];
__device__ float g_GE1[NN*DIM];
__device__ float g_GE2[NN*DIM];
__device__ float g_SQ [NN];
__device__ ull   g_CAND[(size_t)NN*NT*KNN];
__device__ int   g_NBR[NN*KNN];
__device__ float g_A  [NN*DIM];
__device__ float g_B  [NN*DIM];
__device__ float g_ACC1[NN*DIM];
__device__ float g_ACC2[NN*DIM];

__device__ __forceinline__ int swz4(int c)  { return c ^ (c >> 3); }

__device__ __forceinline__ void ffma2(ull &d, ull a, ull b) {
    asm("fma.rn.f32x2 %0, %1, %2, %0;" : "+l"(d) : "l"(a), "l"(b));
}
__device__ __forceinline__ ull dup2(float x) {
    ull r;
    asm("mov.b64 %0, {%1, %1};" : "=l"(r) : "f"(x));
    return r;
}
union P2 { ull q; float2 f; };

// ---------------- pre_fc + embed1 + sq ----------------
__global__ void k_prefc(const float* __restrict__ x,
                        const float* __restrict__ Wp, const float* __restrict__ bp,
                        const float* __restrict__ Wd, const float* __restrict__ bd) {
    int v = blockIdx.x;
    int o = threadIdx.x;           // 64 threads
    __shared__ float xr[32];
    __shared__ float x1r[64];
    __shared__ float red[64];
    if (o < 32) xr[o] = x[v*32 + o];
    __syncthreads();
    float acc = bp[o];
#pragma unroll
    for (int d = 0; d < 32; d++) acc = fmaf(xr[d], Wp[d*64 + o], acc);
    acc = acc > 0.f ? acc : 0.1f * acc;          // LeakyReLU(0.1)
    g_X1[v*64 + o] = acc;
    x1r[o] = acc;
    __syncthreads();
    float ge = bd[o];
#pragma unroll
    for (int d = 0; d < 64; d++) ge = fmaf(x1r[d], Wd[d*64 + o], ge);
    g_GE1[v*64 + o] = ge;
    red[o] = ge * ge;
    __syncthreads();
    for (int s = 32; s > 0; s >>= 1) { if (o < s) red[o] += red[o + s]; __syncthreads(); }
    if (o == 0) g_SQ[v] = red[0];
}

// ---------------- embed2 (concat(GE1, X2) @ W_d2) + sq ----------------
__global__ void k_embed2(const float* __restrict__ Wd, const float* __restrict__ bd) {
    int v = blockIdx.x, o = threadIdx.x;   // 64 threads
    __shared__ float gr[128];
    __shared__ float red[64];
    gr[o]      = g_GE1 [v*64 + o];
    gr[64 + o] = g_ACC1[v*64 + o];
    __syncthreads();
    float ge = bd[o];
#pragma unroll
    for (int d = 0; d < 128; d++) ge = fmaf(gr[d], Wd[d*64 + o], ge);
    g_GE2[v*64 + o] = ge;
    red[o] = ge * ge;
    __syncthreads();
    for (int s = 32; s > 0; s >>= 1) { if (o < s) red[o] += red[o + s]; __syncthreads(); }
    if (o == 0) g_SQ[v] = red[0];
}

// ---- merge two sorted 5-lists held by adjacent lanes (xor 1) ----
__device__ __forceinline__ void merge_pair(ull best[KNN]) {
    ull other[KNN];
#pragma unroll
    for (int j = 0; j < KNN; j++) other[j] = __shfl_xor_sync(0xffffffffu, best[j], 1);
#pragma unroll
    for (int j = 0; j < KNN; j++) {
        ull key = other[j];
        if (key < best[KNN-1]) {
            best[KNN-1] = key;
#pragma unroll
            for (int u = KNN-1; u > 0; u--)
                if (best[u] < best[u-1]) {
                    ull t2 = best[u]; best[u] = best[u-1]; best[u-1] = t2;
                }
        }
    }
}

// ============ fused symmetric distance GEMM + per-tile top-5 (SIMT, exact fp32) ============
__global__ void __launch_bounds__(256, 2)
k_fused(int layer) {
    extern __shared__ float sm[];
    float* As = sm;                 // [32 k][128 rows] chunk-swizzled
    float* Bs = sm + 32*128;
    float* Ds = sm + 64*128;        // [128][PADW]

    const float* GE = layer ? g_GE2 : g_GE1;
    int item = blockIdx.x;
    int bb  = item / NITEMS_B;
    int tri = item - bb*NITEMS_B;
    int rt = 0;
    while (tri >= NT - rt) { tri -= NT - rt; rt++; }
    int ct = rt + tri;

    const float* G  = GE + bb*NPTS*DIM;
    const float* sq = g_SQ + bb*NPTS;
    int tid = threadIdx.x;
    int ty = tid >> 4, tx = tid & 15;
    int r32 = tid & 31;
    int kq2 = tid >> 5;
    const float4* G4 = (const float4*)G;
    const float4* As4 = (const float4*)As;
    const ulonglong2* Bs8 = (const ulonglong2*)Bs;
    int pa0 = swz4(2*ty), pa1 = swz4(2*ty+1);
    int pb0 = swz4(2*tx), pb1 = swz4(2*tx+1);

    ull acc[8][4];
#pragma unroll
    for (int u = 0; u < 8; u++)
#pragma unroll
        for (int v = 0; v < 4; v++) acc[u][v] = 0ULL;

#pragma unroll
    for (int chunk = 0; chunk < 2; chunk++) {
        if (chunk) __syncthreads();
#pragma unroll
        for (int it = 0; it < 4; it++) {
            int row = it*32 + r32;
            float4 va = G4[(rt*128 + row)*16 + chunk*8 + kq2];
            float4 vb = G4[(ct*128 + row)*16 + chunk*8 + kq2];
            int base = swz4(row >> 2)*4 + (row & 3);
            As[(kq2*4+0)*128 + base] = va.x;
            As[(kq2*4+1)*128 + base] = va.y;
            As[(kq2*4+2)*128 + base] = va.z;
            As[(kq2*4+3)*128 + base] = va.w;
            Bs[(kq2*4+0)*128 + base] = vb.x;
            Bs[(kq2*4+1)*128 + base] = vb.y;
            Bs[(kq2*4+2)*128 + base] = vb.z;
            Bs[(kq2*4+3)*128 + base] = vb.w;
        }
        __syncthreads();
#pragma unroll 8
        for (int k = 0; k < 32; k++) {
            float4 a0 = As4[k*32 + pa0];
            float4 a1 = As4[k*32 + pa1];
            ulonglong2 vb0 = Bs8[k*32 + pb0];
            ulonglong2 vb1 = Bs8[k*32 + pb1];
            ull ad[8];
            ad[0] = dup2(a0.x); ad[1] = dup2(a0.y); ad[2] = dup2(a0.z); ad[3] = dup2(a0.w);
            ad[4] = dup2(a1.x); ad[5] = dup2(a1.y); ad[6] = dup2(a1.z); ad[7] = dup2(a1.w);
            ull bp[4] = {vb0.x, vb0.y, vb1.x, vb1.y};
#pragma unroll
            for (int u = 0; u < 8; u++)
#pragma unroll
                for (int v = 0; v < 4; v++)
                    ffma2(acc[u][v], ad[u], bp[v]);
        }
    }

    // --- distances to smem (selection monotone in t; omit it) ---
    float sqr[8], sqc[8];
#pragma unroll
    for (int u = 0; u < 8; u++) sqr[u] = sq[rt*128 + ty*8 + u];
#pragma unroll
    for (int v = 0; v < 8; v++) sqc[v] = sq[ct*128 + tx*8 + v];
#pragma unroll
    for (int u = 0; u < 8; u++) {
        int r = ty*8 + u;
        float dd[8];
#pragma unroll
        for (int vp = 0; vp < 4; vp++) {
            P2 w; w.q = acc[u][vp];
            dd[2*vp]   = fmaxf(sqr[u] + sqc[2*vp]   - 2.f*w.f.x, 0.f);
            dd[2*vp+1] = fmaxf(sqr[u] + sqc[2*vp+1] - 2.f*w.f.y, 0.f);
        }
        float4 d0 = {dd[0], dd[1], dd[2], dd[3]};
        float4 d1 = {dd[4], dd[5], dd[6], dd[7]};
        *(float4*)(Ds + r*PADW + tx*8)     = d0;
        *(float4*)(Ds + r*PADW + tx*8 + 4) = d1;
    }
    __syncthreads();

    // --- row scan ---
    {
        int r = tid >> 1, h = tid & 1;
        ull best[KNN];
#pragma unroll
        for (int j = 0; j < KNN; j++) best[j] = ~0ULL;
        for (int c2 = 0; c2 < 64; c2++) {
            int col = h + 2*c2;
            float d = Ds[r*PADW + col];
            ull key = ((ull)__float_as_uint(d) << 32) | (unsigned)(ct*128 + col);
            if (key < best[KNN-1]) {
                best[KNN-1] = key;
#pragma unroll
                for (int j = KNN-1; j > 0; j--)
                    if (best[j] < best[j-1]) {
                        ull t2 = best[j]; best[j] = best[j-1]; best[j-1] = t2;
                    }
            }
        }
        merge_pair(best);
        if (h == 0) {
            size_t rowg = (size_t)(bb*NPTS + rt*128 + r);
#pragma unroll
            for (int j = 0; j < KNN; j++) g_CAND[(rowg*NT + ct)*KNN + j] = best[j];
        }
    }
    // --- col scan (off-diagonal) ---
    if (rt != ct) {
        int c = tid >> 1, h = tid & 1;
        ull best[KNN];
#pragma unroll
        for (int j = 0; j < KNN; j++) best[j] = ~0ULL;
        for (int r2 = 0; r2 < 64; r2++) {
            int row = h + 2*r2;
            float d = Ds[row*PADW + c];
            ull key = ((ull)__float_as_uint(d) << 32) | (unsigned)(rt*128 + row);
            if (key < best[KNN-1]) {
                best[KNN-1] = key;
#pragma unroll
                for (int j = KNN-1; j > 0; j--)
                    if (best[j] < best[j-1]) {
                        ull t2 = best[j]; best[j] = best[j-1]; best[j-1] = t2;
                    }
            }
        }
        merge_pair(best);
        if (h == 0) {
            size_t rowg = (size_t)(bb*NPTS + ct*128 + c);
#pragma unroll
            for (int j = 0; j < KNN; j++) g_CAND[(rowg*NT + rt)*KNN + j] = best[j];
        }
    }
}

// -------- merge 32 sorted 5-lists per row -> NBR, then logprobs --------
__global__ void k_merge_lp(int layer, const float* __restrict__ tptr,
                           float* __restrict__ lp_out) {
    int gw   = (blockIdx.x * blockDim.x + threadIdx.x) >> 5;   // row
    int lane = threadIdx.x & 31;
    if (gw >= NN) return;
    int bb = gw >> 12, jj = gw & 4095;
    const ull* cp = g_CAND + ((size_t)gw*NT + lane)*KNN;
    ull keys[KNN];
#pragma unroll
    for (int j = 0; j < KNN; j++) keys[j] = cp[j];
    unsigned nbr[KNN];
#pragma unroll
    for (int r = 0; r < KNN; r++) {
        ull cand = keys[0];
        ull m = cand;
#pragma unroll
        for (int off = 16; off; off >>= 1) {
            ull o = __shfl_xor_sync(0xffffffffu, m, off);
            if (o < m) m = o;
        }
        if (m == cand) {
#pragma unroll
            for (int j = 0; j < KNN-1; j++) keys[j] = keys[j+1];
            keys[KNN-1] = ~0ULL;
        }
        nbr[r] = (unsigned)(m & 0xffffffffu);
        if (lane == 0) g_NBR[gw*KNN + r] = (int)nbr[r];
    }
    const float* GE = layer ? g_GE2 : g_GE1;
    float tv = tptr[0]; tv = fminf(fmaxf(tv, -5.f), 5.f);
    float t = expf(tv);
#pragma unroll
    for (int r = 0; r < KNN; r++) {
        int a  = (int)nbr[r];
        int mf = r*NPTS + jj;
        int p  = mf / KNN, q = mf - p*KNN;
        const float* ga = GE + (bb*NPTS + a)*DIM;
        const float* gp = GE + (bb*NPTS + p)*DIM;
        float s = 0.f;
#pragma unroll
        for (int u = 0; u < 2; u++) {
            float d = ga[lane + 32*u] - gp[lane + 32*u];
            s = fmaf(d, d, s);
        }
#pragma unroll
        for (int off = 16; off; off >>= 1) s += __shfl_xor_sync(0xffffffffu, s, off);
        if (lane == 0)
            lp_out[((bb*NPTS + p)*KNN + q)*2 + layer] = -s * t;
    }
}

// ------- EdgeConv node pre-GEMM: 64 nodes x 128 outs per block, grid 128 -------
// A = X @ (Wtop - Wbot), B = X @ Wbot; also zero ACC.
__global__ void __launch_bounds__(256)
k_AB(int layer, const float* __restrict__ W) {
    extern __shared__ float sm[];
    float* Xs = sm;              // [64 k][68] node-major within k
    float* Ws = sm + 64*68;      // [64 k][136] out cols (0..63 A', 64..127 Wbot)
    const float* X = layer ? g_ACC1 : g_X1;
    float* ACC = layer ? g_ACC2 : g_ACC1;
    int tid = threadIdx.x;
    int nt = blockIdx.x;         // 64-node tile

    // stage X tile k-major: 64 nodes x 16 float4
    const float4* X4 = (const float4*)X;
#pragma unroll
    for (int it = 0; it < 4; it++) {
        int idx = tid + it*256;          // 0..1023
        int row = idx >> 4, kq = idx & 15;
        float4 v = X4[((size_t)nt*64 + row)*16 + kq];
        Xs[(kq*4+0)*68 + row] = v.x;
        Xs[(kq*4+1)*68 + row] = v.y;
        Xs[(kq*4+2)*68 + row] = v.z;
        Xs[(kq*4+3)*68 + row] = v.w;
    }
    // stage W: col<64 -> Wtop-Wbot ; col>=64 -> Wbot
#pragma unroll
    for (int i = 0; i < 32; i++) {
        int idx = tid + i*256;           // 0..8191
        int k = idx >> 7, col = idx & 127;
        float val = (col < 64) ? (W[k*64 + col] - W[(64 + k)*64 + col])
                               : W[(64 + k)*64 + (col - 64)];
        Ws[k*136 + col] = val;
    }
    __syncthreads();

    int ty = tid >> 4, tx = tid & 15;    // ty: 4-node group, tx: 4-out group
    float acc[4][8];
#pragma unroll
    for (int u = 0; u < 4; u++)
#pragma unroll
        for (int v = 0; v < 8; v++) acc[u][v] = 0.f;
#pragma unroll 8
    for (int k = 0; k < 64; k++) {
        float4 a  = *(const float4*)(Xs + k*68 + ty*4);
        float4 b0 = *(const float4*)(Ws + k*136 + tx*4);         // A' cols
        float4 b1 = *(const float4*)(Ws + k*136 + 64 + tx*4);    // Wbot cols
        float av[4] = {a.x, a.y, a.z, a.w};
#pragma unroll
        for (int u = 0; u < 4; u++) {
            acc[u][0] = fmaf(av[u], b0.x, acc[u][0]);
            acc[u][1] = fmaf(av[u], b0.y, acc[u][1]);
            acc[u][2] = fmaf(av[u], b0.z, acc[u][2]);
            acc[u][3] = fmaf(av[u], b0.w, acc[u][3]);
            acc[u][4] = fmaf(av[u], b1.x, acc[u][4]);
            acc[u][5] = fmaf(av[u], b1.y, acc[u][5]);
            acc[u][6] = fmaf(av[u], b1.z, acc[u][6]);
            acc[u][7] = fmaf(av[u], b1.w, acc[u][7]);
        }
    }
#pragma unroll
    for (int u = 0; u < 4; u++) {
        int node = nt*64 + ty*4 + u;
        float4 aout = {acc[u][0], acc[u][1], acc[u][2], acc[u][3]};
        float4 bout = {acc[u][4], acc[u][5], acc[u][6], acc[u][7]};
        *(float4*)(g_A + (size_t)node*64 + tx*4) = aout;
        *(float4*)(g_B + (size_t)node*64 + tx*4) = bout;
        float4 z = {0.f, 0.f, 0.f, 0.f};
        *(float4*)(ACC + (size_t)node*64 + tx*4) = z;
    }
}

// ---------------- EdgeConv scatter-max ----------------
__global__ void k_scatter(int layer, const float* __restrict__ bias) {
    int tid = blockIdx.x * blockDim.x + threadIdx.x;
    if (tid >= NEDGE * 2) return;
    int s  = tid >> 1, h = tid & 1;
    int p0 = s >> 2, bb = (s >> 1) & 1, c = s & 1;
    int src, dst;
    if (c == 0) src = g_NBR[(bb*NPTS + (p0 & 4095))*KNN + (p0 >> 12)] + bb*NPTS;
    else        src = p0 / KNN + bb*NPTS;
    int p1 = p0 + NKM/2;
    if (c == 0) dst = g_NBR[(bb*NPTS + (p1 & 4095))*KNN + (p1 >> 12)] + bb*NPTS;
    else        dst = p1 / KNN + bb*NPTS;

    float* ACC = layer ? g_ACC2 : g_ACC1;
    const float4* Ad = (const float4*)(g_A + dst*64 + h*32);
    const float4* Bv = (const float4*)(g_B + src*64 + h*32);
    const float4* Bi = (const float4*)(bias + h*32);
    int* out = (int*)(ACC + dst*64 + h*32);
#pragma unroll
    for (int o = 0; o < 8; o++) {
        float4 av = Ad[o], bv = Bv[o], bi = Bi[o];
        float m0 = av.x + bv.x + bi.x;
        float m1 = av.y + bv.y + bi.y;
        float m2 = av.z + bv.z + bi.z;
        float m3 = av.w + bv.w + bi.w;
        if (m0 > 0.f) atomicMax(&out[o*4 + 0], __float_as_int(m0));
        if (m1 > 0.f) atomicMax(&out[o*4 + 1], __float_as_int(m1));
        if (m2 > 0.f) atomicMax(&out[o*4 + 2], __float_as_int(m2));
        if (m3 > 0.f) atomicMax(&out[o*4 + 3], __float_as_int(m3));
    }
}

// ---------------- final MLP 64 -> 32 -> 8 ----------------
__global__ void k_fc(const float* __restrict__ W1, const float* __restrict__ b1,
                     const float* __restrict__ W2, const float* __restrict__ b2,
                     float* __restrict__ out) {
    int v = blockIdx.x, o = threadIdx.x;   // 32 threads
    __shared__ float xr[64];
    __shared__ float hr[32];
    xr[o]      = g_ACC2[v*64 + o];
    xr[32 + o] = g_ACC2[v*64 + 32 + o];
    __syncthreads();
    float hh = b1[o];
#pragma unroll
    for (int d = 0; d < 64; d++) hh = fmaf(xr[d], W1[d*32 + o], hh);
    hh = hh > 0.f ? hh : 0.1f * hh;
    hr[o] = hh;
    __syncthreads();
    if (o < 8) {
        float acc = b2[o];
#pragma unroll
        for (int d = 0; d < 32; d++) acc = fmaf(hr[d], W2[d*8 + o], acc);
        out[v*8 + o] = acc;
    }
}

// ======================= launcher =======================
extern "C" void kernel_launch(void* const* d_in, const int* in_sizes, int n_in,
                              void* d_out, int out_size) {
    const float* x     = (const float*)d_in[0];
    const float* W_pre = (const float*)d_in[1];
    const float* b_pre = (const float*)d_in[2];
    const float* W_d1  = (const float*)d_in[3];
    const float* b_d1  = (const float*)d_in[4];
    const float* t1    = (const float*)d_in[5];
    const float* W_c1  = (const float*)d_in[6];
    const float* b_c1  = (const float*)d_in[7];
    const float* W_d2  = (const float*)d_in[8];
    const float* b_d2  = (const float*)d_in[9];
    const float* t2    = (const float*)d_in[10];
    const float* W_c2  = (const float*)d_in[11];
    const float* b_c2  = (const float*)d_in[12];
    const float* W_f1  = (const float*)d_in[13];
    const float* b_f1  = (const float*)d_in[14];
    const float* W_f2  = (const float*)d_in[15];
    const float* b_f2  = (const float*)d_in[16];

    float* out = (float*)d_out;                 // [2,4096,8]
    float* lp  = out + NN * 8;                  // [2,4096,5,2]

    cudaFuncSetAttribute(k_fused, cudaFuncAttributeMaxDynamicSharedMemorySize, SMEMF);
    cudaFuncSetAttribute(k_AB,    cudaFuncAttributeMaxDynamicSharedMemorySize, SMEMAB);

    // layer 1
    k_prefc<<<NN, 64>>>(x, W_pre, b_pre, W_d1, b_d1);
    k_fused<<<NITEMS, 256, SMEMF>>>(0);
    k_merge_lp<<<NN/8, 256>>>(0, t1, lp);
    k_AB<<<NN/64, 256, SMEMAB>>>(0, W_c1);
    k_scatter<<<(NEDGE*2 + 255)/256, 256>>>(0, b_c1);

    // layer 2
    k_embed2<<<NN, 64>>>(W_d2, b_d2);
    k_fused<<<NITEMS, 256, SMEMF>>>(1);
    k_merge_lp<<<NN/8, 256>>>(1, t2, lp);
    k_AB<<<NN/64, 256, SMEMAB>>>(1, W_c2);
    k_scatter<<<(NEDGE*2 + 255)/256, 256>>>(1, b_c2);

    // head
    k_fc<<<NN, 32>>>(W_f1, b_f1, W_f2, b_f2, out);
}